// round 11
// baseline (speedup 1.0000x reference)
#include <cuda_runtime.h>
#include <cstdint>

#define BN_SCALE 0.9999950000374997f
#define FLTMAX 3.402823466e+38f

typedef unsigned long long u64;

// packed fp32x2 helpers — bit-exact IEEE fp32 per lane
__device__ __forceinline__ void fma2(u64& d, u64 a, u64 b) {
    asm("fma.rn.f32x2 %0,%1,%2,%0;" : "+l"(d) : "l"(a), "l"(b));
}
__device__ __forceinline__ float2 unpk(u64 v) {
    float2 r; asm("mov.b64 {%0,%1},%2;" : "=f"(r.x), "=f"(r.y) : "l"(v)); return r;
}
__device__ __forceinline__ u64 pk2(float v) {
    u64 r; asm("mov.b64 %0,{%1,%1};" : "=l"(r) : "f"(v)); return r;
}

// ---- (d, j) packed key: exact lexicographic (d asc, j asc) ----
__device__ __forceinline__ u64 packdj(float d, int j) {
    unsigned u = __float_as_uint(d);
    u = ((int)u < 0) ? ~u : (u | 0x80000000u);
    return ((u64)u << 32) | (unsigned)j;
}
__device__ __forceinline__ void ce(u64& a, u64& b) {
    if (b < a) { u64 t = a; a = b; b = t; }
}
__device__ __forceinline__ void sort8(u64 k[8]) {
    ce(k[0],k[1]); ce(k[2],k[3]); ce(k[4],k[5]); ce(k[6],k[7]);
    ce(k[0],k[2]); ce(k[1],k[3]); ce(k[4],k[6]); ce(k[5],k[7]);
    ce(k[1],k[2]); ce(k[5],k[6]);
    ce(k[0],k[4]); ce(k[1],k[5]); ce(k[2],k[6]); ce(k[3],k[7]);
    ce(k[2],k[4]); ce(k[3],k[5]);
    ce(k[1],k[2]); ce(k[3],k[4]); ce(k[5],k[6]);
}
// sort a bitonic 16-sequence ascending (4 stages, 32 CE)
__device__ __forceinline__ void bitonic16(u64 c[16]) {
    #pragma unroll
    for (int d = 8; d; d >>= 1)
        #pragma unroll
        for (int i = 0; i < 16; i++)
            if ((i & d) == 0) ce(c[i], c[i + d]);
}
// warp-cooperative lowest-16 of 256 keys (lane holds sorted-8 in k).
// After return, ALL lanes hold the global sorted lowest-16 in c[0..15].
__device__ __forceinline__ void topk16_merge(const u64 k[8], u64 c[16]) {
    // round 1 (dist 1): full merge of two sorted-8 -> sorted-16
    u64 pb[8];
    #pragma unroll
    for (int u = 0; u < 8; ++u) pb[u] = __shfl_xor_sync(0xFFFFFFFFu, k[u], 1);
    #pragma unroll
    for (int u = 0; u < 8; ++u) { c[u] = k[u]; c[15 - u] = pb[u]; }
    bitonic16(c);
    // rounds 2..5 (dist 2,4,8,16): keep lowest-16 of two sorted-16
    #pragma unroll
    for (int o = 2; o <= 16; o <<= 1) {
        u64 q[16];
        #pragma unroll
        for (int i = 0; i < 16; ++i) q[i] = __shfl_xor_sync(0xFFFFFFFFu, c[i], o);
        u64 t[16];
        #pragma unroll
        for (int i = 0; i < 16; ++i) {
            u64 a = c[i], b = q[15 - i];
            t[i] = (b < a) ? b : a;
        }
        #pragma unroll
        for (int i = 0; i < 16; ++i) c[i] = t[i];
        bitonic16(c);
    }
}
__device__ __forceinline__ void write16(int* op, const u64 c[16]) {
    #pragma unroll
    for (int g = 0; g < 4; ++g) {
        int4 v;
        v.x = (int)(unsigned)c[4 * g + 0];
        v.y = (int)(unsigned)c[4 * g + 1];
        v.z = (int)(unsigned)c[4 * g + 2];
        v.w = (int)(unsigned)c[4 * g + 3];
        *(int4*)&op[4 * g] = v;
    }
}

// ------------------------- device scratch -------------------------
__device__ float g_T[32768 * 512];
__device__ float g_h1[32768 * 64];
__device__ float g_h2[32768 * 128];
__device__ float g_h3[32768 * 256];
__device__ int   g_idx[128 * 256 * 16];
__device__ float g_W1p[6 * 128];   __device__ float g_b1p[128];
__device__ float g_W2p[64 * 256];  __device__ float g_b2p[256];
__device__ float g_W3p[128 * 512]; __device__ float g_b3p[512];

// ------------------------- weight prep ----------------------------
__global__ void prepw(const float* __restrict__ W, const float* __restrict__ b,
                      const float* __restrict__ g, const float* __restrict__ be,
                      float* __restrict__ Wp, float* __restrict__ bp,
                      int Cin, int C) {
    int n2 = 2 * C;
    int total = Cin * n2;
    for (int t = blockIdx.x * blockDim.x + threadIdx.x; t < total + n2;
         t += gridDim.x * blockDim.x) {
        if (t < total) {
            int k = t / n2, c = t % n2;
            float out;
            if (c < C) out = g[c] * BN_SCALE * (W[k * C + c] - W[(Cin + k) * C + c]);
            else { int cc = c - C; out = g[cc] * BN_SCALE * W[(Cin + k) * C + cc]; }
            Wp[t] = out;
        } else {
            int c = t - total;
            bp[c] = (c < C) ? (g[c] * BN_SCALE * b[c] + be[c]) : 0.0f;
        }
    }
}

// ------------------------- fused KNN, D=6 (layer 1) ---------------
// grid (8, 128): batch blockIdx.y, row-group blockIdx.x (32 rows).
// warp handles 4 rows; lane covers candidates j = u*32+lane.
__global__ __launch_bounds__(256) void knn6(const float* __restrict__ X,
                                            int* __restrict__ idx) {
    __shared__ float pts[6][256];
    __shared__ float sqs[256];
    int b = blockIdx.y, q = blockIdx.x;
    int tid = threadIdx.x;
    {
        const float* xp = X + ((size_t)b * 256 + tid) * 6;
        float s = 0.0f;
        #pragma unroll
        for (int k = 0; k < 6; k++) { float v = xp[k]; pts[k][tid] = v; s += v * v; }
        sqs[tid] = s;
    }
    __syncthreads();
    int warp = tid >> 5, lane = tid & 31;
    for (int rr = 0; rr < 4; ++rr) {
        int i = q * 32 + warp * 4 + rr;
        float x0 = pts[0][i], x1 = pts[1][i], x2 = pts[2][i];
        float x3 = pts[3][i], x4 = pts[4][i], x5 = pts[5][i];
        float sqi = sqs[i];
        u64 k[8];
        #pragma unroll
        for (int u = 0; u < 8; ++u) {
            int j = u * 32 + lane;
            float dot = x0 * pts[0][j] + x1 * pts[1][j] + x2 * pts[2][j]
                      + x3 * pts[3][j] + x4 * pts[4][j] + x5 * pts[5][j];
            float d = sqi + sqs[j] - 2.0f * dot;
            if (j == i) d = FLTMAX;
            k[u] = packdj(d, j);
        }
        sort8(k);
        u64 c[16];
        topk16_merge(k, c);
        if (lane == 0) write16(idx + ((size_t)b * 256 + i) * 16, c);
    }
}

// ------------------------- fused KNN, D in {64,128} ---------------
template<int D>
__global__ __launch_bounds__(256) void knnf(const float* __restrict__ H,
                                            int* __restrict__ idx) {
    extern __shared__ float sm[];
    float* sqs = sm;                 // 256
    float* As  = sm + 256;           // 2*16*68  = 2176
    float* Bs  = sm + 256 + 2176;    // 2*16*132 = 4224
    float* ds  = sm + 256 + 2176 + 4224; // 64*260 = 16640
    int b = blockIdx.y;
    int i0 = blockIdx.x * 64;
    const float* Hb = H + (size_t)b * 256 * D;
    int tid = threadIdx.x;
    int ty = tid >> 5, tx = tid & 31;

    {
        const float4* rp = (const float4*)(Hb + (size_t)tid * D);
        float s = 0.0f;
        #pragma unroll
        for (int u = 0; u < D / 4; ++u) {
            float4 v = rp[u];
            s += v.x * v.x + v.y * v.y + v.z * v.z + v.w * v.w;
        }
        sqs[tid] = s;
    }

    int ar = tid & 63,  ak4 = (tid >> 6) * 4;
    int br = tid & 127, bk8 = (tid >> 7) * 8;

    for (int h = 0; h < 2; ++h) {
        int j0 = h * 128;
        u64 acc2[4][4];
        #pragma unroll
        for (int p = 0; p < 4; p++)
            #pragma unroll
            for (int s = 0; s < 4; s++) acc2[p][s] = 0ull;

        float4 pa  = *(const float4*)(Hb + (size_t)(i0 + ar) * D + ak4);
        float4 pb0 = *(const float4*)(Hb + (size_t)(j0 + br) * D + bk8);
        float4 pb1 = *(const float4*)(Hb + (size_t)(j0 + br) * D + bk8 + 4);
        int buf = 0;

        for (int k0 = 0; k0 < D; k0 += 16) {
            float* Ab = As + buf * 1088;
            float* Bb = Bs + buf * 2112;
            Ab[(ak4 + 0) * 68 + ar] = pa.x;
            Ab[(ak4 + 1) * 68 + ar] = pa.y;
            Ab[(ak4 + 2) * 68 + ar] = pa.z;
            Ab[(ak4 + 3) * 68 + ar] = pa.w;
            Bb[(bk8 + 0) * 132 + br] = pb0.x;
            Bb[(bk8 + 1) * 132 + br] = pb0.y;
            Bb[(bk8 + 2) * 132 + br] = pb0.z;
            Bb[(bk8 + 3) * 132 + br] = pb0.w;
            Bb[(bk8 + 4) * 132 + br] = pb1.x;
            Bb[(bk8 + 5) * 132 + br] = pb1.y;
            Bb[(bk8 + 6) * 132 + br] = pb1.z;
            Bb[(bk8 + 7) * 132 + br] = pb1.w;
            __syncthreads();
            if (k0 + 16 < D) {
                pa  = *(const float4*)(Hb + (size_t)(i0 + ar) * D + k0 + 16 + ak4);
                pb0 = *(const float4*)(Hb + (size_t)(j0 + br) * D + k0 + 16 + bk8);
                pb1 = *(const float4*)(Hb + (size_t)(j0 + br) * D + k0 + 16 + bk8 + 4);
            }
            #pragma unroll
            for (int kk = 0; kk < 16; ++kk) {
                float4 a0 = *(const float4*)&Ab[kk * 68 + ty * 8];
                float4 a1 = *(const float4*)&Ab[kk * 68 + ty * 8 + 4];
                u64 ap[4];
                ap[0] = ((const u64*)&a0)[0]; ap[1] = ((const u64*)&a0)[1];
                ap[2] = ((const u64*)&a1)[0]; ap[3] = ((const u64*)&a1)[1];
                float4 bv = *(const float4*)&Bb[kk * 132 + tx * 4];
                u64 bd0 = pk2(bv.x), bd1 = pk2(bv.y), bd2 = pk2(bv.z), bd3 = pk2(bv.w);
                #pragma unroll
                for (int p = 0; p < 4; p++) {
                    fma2(acc2[p][0], ap[p], bd0);
                    fma2(acc2[p][1], ap[p], bd1);
                    fma2(acc2[p][2], ap[p], bd2);
                    fma2(acc2[p][3], ap[p], bd3);
                }
            }
            buf ^= 1;
        }

        #pragma unroll
        for (int p = 0; p < 4; p++) {
            float2 c0 = unpk(acc2[p][0]);
            float2 c1 = unpk(acc2[p][1]);
            float2 c2 = unpk(acc2[p][2]);
            float2 c3 = unpk(acc2[p][3]);
            int col = j0 + tx * 4;
            #pragma unroll
            for (int e = 0; e < 2; e++) {
                int row = ty * 8 + 2 * p + e;
                float si = sqs[i0 + row];
                float d0 = (e == 0) ? c0.x : c0.y;
                float d1 = (e == 0) ? c1.x : c1.y;
                float d2_ = (e == 0) ? c2.x : c2.y;
                float d3 = (e == 0) ? c3.x : c3.y;
                float4 v;
                v.x = si + sqs[col + 0] - 2.0f * d0;
                v.y = si + sqs[col + 1] - 2.0f * d1;
                v.z = si + sqs[col + 2] - 2.0f * d2_;
                v.w = si + sqs[col + 3] - 2.0f * d3;
                int gi = i0 + row;
                if (gi == col + 0) v.x = FLTMAX;
                if (gi == col + 1) v.y = FLTMAX;
                if (gi == col + 2) v.z = FLTMAX;
                if (gi == col + 3) v.w = FLTMAX;
                *(float4*)&ds[row * 260 + col] = v;
            }
        }
    }
    __syncthreads();

    // warp-parallel top-16 via merge network: warp w rows w*8..w*8+7
    {
        int warp = tid >> 5, lane = tid & 31;
        for (int rr = 0; rr < 8; ++rr) {
            int row = warp * 8 + rr;
            const float* dr = &ds[row * 260];
            u64 k[8];
            #pragma unroll
            for (int u = 0; u < 8; ++u) {
                int j = u * 32 + lane;
                k[u] = packdj(dr[j], j);
            }
            sort8(k);
            u64 c[16];
            topk16_merge(k, c);
            if (lane == 0) write16(idx + ((size_t)b * 256 + i0 + row) * 16, c);
        }
    }
}

// ------------------------- layer-1 SGEMM (K=6, N=128) -------------
__global__ __launch_bounds__(256) void sgemm6(const float* __restrict__ X,
                                              const float* __restrict__ Wp,
                                              const float* __restrict__ bp,
                                              float* __restrict__ T) {
    __shared__ float Ws[6][128];
    __shared__ float bs[128];
    int tid = threadIdx.x;
    if (tid < 128) bs[tid] = bp[tid];
    for (int t = tid; t < 768; t += 256) Ws[t / 128][t % 128] = Wp[t];
    __syncthreads();
    int warp = tid >> 5, lane = tid & 31;
    int row = blockIdx.x * 8 + warp;
    const float* xr = X + (size_t)row * 6;
    float x0 = xr[0], x1 = xr[1], x2 = xr[2], x3 = xr[3], x4 = xr[4], x5 = xr[5];
    int c = lane * 4;
    float4 o;
    #pragma unroll
    for (int u = 0; u < 4; ++u) {
        float v = bs[c + u];
        v += x0 * Ws[0][c + u]; v += x1 * Ws[1][c + u]; v += x2 * Ws[2][c + u];
        v += x3 * Ws[3][c + u]; v += x4 * Ws[4][c + u]; v += x5 * Ws[5][c + u];
        ((float*)&o)[u] = v;
    }
    *(float4*)&T[(size_t)row * 128 + c] = o;
}

// ------------------------- main SGEMM -----------------------------
// 128 threads, 128x128 block tile, 16 rows x 8 cols per thread, FFMA2
// with pre-duplicated B in smem (1 B/MAC at the doubled FFMA2 rate).
__global__ __launch_bounds__(128) void sgemm(const float* __restrict__ A,
                                             const float* __restrict__ W,
                                             const float* __restrict__ bias,
                                             float* __restrict__ C,
                                             int K, int N) {
    extern __shared__ float smx[];
    float* Asm = smx;            // [2][16][132]
    float* Bsm = smx + 4224;     // [2][16][264] duplicated
    int i0 = blockIdx.y * 128, j0 = blockIdx.x * 128;
    int tid = threadIdx.x;
    int tx = tid & 15, ty = tid >> 4;
    int bk = tid & 15, bg = (tid >> 4) * 16;

    u64 acc[8][8];
    #pragma unroll
    for (int p = 0; p < 8; p++)
        #pragma unroll
        for (int s = 0; s < 8; s++) acc[p][s] = 0ull;

    const float* Arow = A + (size_t)(i0 + tid) * K;
    float4 ga[4], gb[4];
    #pragma unroll
    for (int u = 0; u < 4; ++u) ga[u] = *(const float4*)&Arow[u * 4];
    #pragma unroll
    for (int u = 0; u < 4; ++u) gb[u] = *(const float4*)&W[(size_t)bk * N + j0 + bg + u * 4];
    {
        float* Aw = Asm; float* Bw = Bsm;
        #pragma unroll
        for (int u = 0; u < 4; ++u) {
            Aw[(u * 4 + 0) * 132 + tid] = ga[u].x;
            Aw[(u * 4 + 1) * 132 + tid] = ga[u].y;
            Aw[(u * 4 + 2) * 132 + tid] = ga[u].z;
            Aw[(u * 4 + 3) * 132 + tid] = ga[u].w;
            float4 v = gb[u];
            *(float4*)&Bw[bk * 264 + 2 * (bg + u * 4)]     = make_float4(v.x, v.x, v.y, v.y);
            *(float4*)&Bw[bk * 264 + 2 * (bg + u * 4) + 4] = make_float4(v.z, v.z, v.w, v.w);
        }
    }
    __syncthreads();

    int nsteps = K >> 4;
    for (int st = 0; st < nsteps; ++st) {
        int buf = st & 1;
        bool more = (st + 1 < nsteps);
        if (more) {
            int k0 = (st + 1) << 4;
            #pragma unroll
            for (int u = 0; u < 4; ++u) ga[u] = *(const float4*)&Arow[k0 + u * 4];
            #pragma unroll
            for (int u = 0; u < 4; ++u) gb[u] = *(const float4*)&W[(size_t)(k0 + bk) * N + j0 + bg + u * 4];
        }
        const float* Ab = Asm + buf * 2112;
        const float* Bb = Bsm + buf * 4224;
        #pragma unroll
        for (int kk = 0; kk < 16; ++kk) {
            const float4* arp = (const float4*)&Ab[kk * 132 + ty * 16];
            float4 a0 = arp[0], a1 = arp[1], a2 = arp[2], a3 = arp[3];
            u64 ap[8];
            ap[0] = ((const u64*)&a0)[0]; ap[1] = ((const u64*)&a0)[1];
            ap[2] = ((const u64*)&a1)[0]; ap[3] = ((const u64*)&a1)[1];
            ap[4] = ((const u64*)&a2)[0]; ap[5] = ((const u64*)&a2)[1];
            ap[6] = ((const u64*)&a3)[0]; ap[7] = ((const u64*)&a3)[1];
            u64 bp[8];
            #pragma unroll
            for (int s = 0; s < 4; ++s) {
                float4 bv = *(const float4*)&Bb[kk * 264 + 4 * tx + 64 * s];
                bp[2 * s]     = ((const u64*)&bv)[0];
                bp[2 * s + 1] = ((const u64*)&bv)[1];
            }
            #pragma unroll
            for (int p = 0; p < 8; p++)
                #pragma unroll
                for (int s = 0; s < 8; s++)
                    fma2(acc[p][s], ap[p], bp[s]);
        }
        if (more) {
            int nb = buf ^ 1;
            float* Aw = Asm + nb * 2112;
            float* Bw = Bsm + nb * 4224;
            #pragma unroll
            for (int u = 0; u < 4; ++u) {
                Aw[(u * 4 + 0) * 132 + tid] = ga[u].x;
                Aw[(u * 4 + 1) * 132 + tid] = ga[u].y;
                Aw[(u * 4 + 2) * 132 + tid] = ga[u].z;
                Aw[(u * 4 + 3) * 132 + tid] = ga[u].w;
                float4 v = gb[u];
                *(float4*)&Bw[bk * 264 + 2 * (bg + u * 4)]     = make_float4(v.x, v.x, v.y, v.y);
                *(float4*)&Bw[bk * 264 + 2 * (bg + u * 4) + 4] = make_float4(v.z, v.z, v.w, v.w);
            }
            __syncthreads();
        }
    }

    #pragma unroll
    for (int p = 0; p < 8; p++) {
        float2 c[8];
        #pragma unroll
        for (int s = 0; s < 8; s++) c[s] = unpk(acc[p][s]);
        #pragma unroll
        for (int e = 0; e < 2; e++) {
            int row = i0 + ty * 16 + 2 * p + e;
            #pragma unroll
            for (int s4 = 0; s4 < 4; s4++) {
                int col = j0 + 2 * tx + 32 * s4;
                float2 v;
                v.x = ((e == 0) ? c[2 * s4].x     : c[2 * s4].y)     + bias[col];
                v.y = ((e == 0) ? c[2 * s4 + 1].x : c[2 * s4 + 1].y) + bias[col + 1];
                *(float2*)&C[(size_t)row * N + col] = v;
            }
        }
    }
}

// ------------------------- edge max -------------------------------
__global__ __launch_bounds__(256) void edgemax(const float* __restrict__ T,
                                               const int* __restrict__ idx,
                                               float* __restrict__ H, int C) {
    __shared__ float sc[256][32];
    int b = blockIdx.x;
    int c0 = blockIdx.y * 32;
    int cc = threadIdx.x & 31;
    int i0 = threadIdx.x >> 5;
    const float* Tb = T + (size_t)b * 256 * 2 * C;

    for (int j = i0; j < 256; j += 8)
        sc[j][cc] = Tb[(size_t)j * 2 * C + C + c0 + cc];
    __syncthreads();

    for (int i = i0; i < 256; i += 8) {
        const int* ip = idx + ((size_t)b * 256 + i) * 16;
        float mx = -FLTMAX;
        #pragma unroll
        for (int k = 0; k < 16; ++k) {
            int j = ip[k];
            mx = fmaxf(mx, sc[j][cc]);
        }
        float a = Tb[(size_t)i * 2 * C + c0 + cc];
        H[((size_t)b * 256 + i) * C + c0 + cc] = fmaxf(a + mx, 0.0f);
    }
}

// ------------------------- head: pool + MLP -----------------------
__global__ __launch_bounds__(256) void finalk(const float* __restrict__ H3,
                                              const float* __restrict__ Wf1,
                                              const float* __restrict__ bf1,
                                              const float* __restrict__ gf,
                                              const float* __restrict__ bef,
                                              const float* __restrict__ Wf2,
                                              const float* __restrict__ bf2,
                                              float* __restrict__ out) {
    __shared__ float p[256];
    __shared__ float f1[128];
    int b = blockIdx.x, t = threadIdx.x;
    const float* Hb = H3 + (size_t)b * 256 * 256;
    float m = -FLTMAX;
    for (int i = 0; i < 256; i++) m = fmaxf(m, Hb[(size_t)i * 256 + t]);
    p[t] = m;
    __syncthreads();
    if (t < 128) {
        float acc = bf1[t];
        for (int k = 0; k < 256; k++) acc += p[k] * Wf1[k * 128 + t];
        f1[t] = fmaxf(gf[t] * (acc * BN_SCALE) + bef[t], 0.0f);
    }
    __syncthreads();
    if (t < 12) {
        float acc = bf2[t];
        for (int k = 0; k < 128; k++) acc += f1[k] * Wf2[k * 12 + t];
        out[b * 12 + t] = acc;
    }
}

// ------------------------- launch ---------------------------------
static const int KNNF_SMEM  = (256 + 2176 + 4224 + 16640) * 4;  // 93,184 B
static const int SGEMM_SMEM = (4224 + 8448) * 4;                // 50,688 B

extern "C" void kernel_launch(void* const* d_in, const int* in_sizes, int n_in,
                              void* d_out, int out_size) {
    const float* x   = (const float*)d_in[0];
    const float* W1  = (const float*)d_in[1];
    const float* b1  = (const float*)d_in[2];
    const float* g1  = (const float*)d_in[3];
    const float* be1 = (const float*)d_in[4];
    const float* W2  = (const float*)d_in[5];
    const float* b2  = (const float*)d_in[6];
    const float* g2  = (const float*)d_in[7];
    const float* be2 = (const float*)d_in[8];
    const float* W3  = (const float*)d_in[9];
    const float* b3  = (const float*)d_in[10];
    const float* g3  = (const float*)d_in[11];
    const float* be3 = (const float*)d_in[12];
    const float* Wf1 = (const float*)d_in[13];
    const float* bf1 = (const float*)d_in[14];
    const float* gf  = (const float*)d_in[15];
    const float* bef = (const float*)d_in[16];
    const float* Wf2 = (const float*)d_in[17];
    const float* bf2 = (const float*)d_in[18];
    float* out = (float*)d_out;

    cudaFuncSetAttribute(knnf<64>,  cudaFuncAttributeMaxDynamicSharedMemorySize, KNNF_SMEM);
    cudaFuncSetAttribute(knnf<128>, cudaFuncAttributeMaxDynamicSharedMemorySize, KNNF_SMEM);
    cudaFuncSetAttribute(sgemm,     cudaFuncAttributeMaxDynamicSharedMemorySize, SGEMM_SMEM);

    void *pT, *ph1, *ph2, *ph3, *pidx;
    void *pW1p, *pb1p, *pW2p, *pb2p, *pW3p, *pb3p;
    cudaGetSymbolAddress(&pT,  g_T);
    cudaGetSymbolAddress(&ph1, g_h1);
    cudaGetSymbolAddress(&ph2, g_h2);
    cudaGetSymbolAddress(&ph3, g_h3);
    cudaGetSymbolAddress(&pidx, g_idx);
    cudaGetSymbolAddress(&pW1p, g_W1p); cudaGetSymbolAddress(&pb1p, g_b1p);
    cudaGetSymbolAddress(&pW2p, g_W2p); cudaGetSymbolAddress(&pb2p, g_b2p);
    cudaGetSymbolAddress(&pW3p, g_W3p); cudaGetSymbolAddress(&pb3p, g_b3p);
    float* T   = (float*)pT;
    float* h1  = (float*)ph1;
    float* h2  = (float*)ph2;
    float* h3  = (float*)ph3;
    int*   idx = (int*)pidx;

    prepw<<<8,   256>>>(W1, b1, g1, be1, (float*)pW1p, (float*)pb1p, 6,   64);
    prepw<<<64,  256>>>(W2, b2, g2, be2, (float*)pW2p, (float*)pb2p, 64,  128);
    prepw<<<256, 256>>>(W3, b3, g3, be3, (float*)pW3p, (float*)pb3p, 128, 256);

    // ---- layer 1 (D=6 -> C=64)
    knn6<<<dim3(8, 128), 256>>>(x, idx);
    sgemm6<<<4096, 256>>>(x, (float*)pW1p, (float*)pb1p, T);
    edgemax<<<dim3(128, 2), 256>>>(T, idx, h1, 64);

    // ---- layer 2 (D=64 -> C=128)
    knnf<64><<<dim3(4, 128), 256, KNNF_SMEM>>>(h1, idx);
    sgemm<<<dim3(2, 256), 128, SGEMM_SMEM>>>(h1, (float*)pW2p, (float*)pb2p, T, 64, 256);
    edgemax<<<dim3(128, 4), 256>>>(T, idx, h2, 128);

    // ---- layer 3 (D=128 -> C=256)
    knnf<128><<<dim3(4, 128), 256, KNNF_SMEM>>>(h2, idx);
    sgemm<<<dim3(4, 256), 128, SGEMM_SMEM>>>(h2, (float*)pW3p, (float*)pb3p, T, 128, 512);
    edgemax<<<dim3(128, 8), 256>>>(T, idx, h3, 256);

    // ---- head
    finalk<<<128, 256>>>(h3, Wf1, bf1, gf, bef, Wf2, bf2, out);
}